// round 16
// baseline (speedup 1.0000x reference)
#include <cuda_runtime.h>
#include <cuda_bf16.h>
#include <math.h>
#include <stdint.h>

#define B_SZ  4096
#define D_IN  1024
#define HID   2048
#define NSEG  10
#define D_CTX 1024
#define D_OUT 1024
#define KWIN  102

// ---------------- scratch (device globals, allocation-free) ----------------
__device__ float g_dend[(size_t)B_SZ * HID * NSEG]; // 4096 x 20480  (~335 MB)
__device__ float g_y[(size_t)B_SZ * HID];           // pre-gate linear output

// bf16 hi/mid/lo splits of every GEMM operand (exact 3-way decomposition)
__device__ __nv_bfloat16 g_xs [3][(size_t)B_SZ * D_IN];
__device__ __nv_bfloat16 g_cs [3][(size_t)B_SZ * D_CTX];
__device__ __nv_bfloat16 g_w1s[3][(size_t)HID * D_IN];
__device__ __nv_bfloat16 g_s1s[3][(size_t)HID * NSEG * D_CTX];
__device__ __nv_bfloat16 g_w2s[3][(size_t)HID * HID];
__device__ __nv_bfloat16 g_s2s[3][(size_t)HID * NSEG * D_CTX];
__device__ __nv_bfloat16 g_wos[3][(size_t)D_OUT * HID];
__device__ __nv_bfloat16 g_hs [3][(size_t)B_SZ * HID];

// ---------------- bf16 3-way split (float4-vectorized) ----------------------
__global__ void split_kernel(const float* __restrict__ src,
                             __nv_bfloat16* __restrict__ hh,
                             __nv_bfloat16* __restrict__ mm,
                             __nv_bfloat16* __restrict__ ll, size_t n)
{
    const size_t n4 = n >> 2;
    for (size_t i = (size_t)blockIdx.x * blockDim.x + threadIdx.x; i < n4;
         i += (size_t)gridDim.x * blockDim.x) {
        float4 a = ((const float4*)src)[i];
        float av[4] = {a.x, a.y, a.z, a.w};
        __nv_bfloat16 hv[4], mv[4], lv[4];
#pragma unroll
        for (int j = 0; j < 4; j++) {
            float v = av[j];
            __nv_bfloat16 hb = __float2bfloat16(v);
            float hf = __bfloat162float(hb);
            float r1 = v - hf;                       // exact
            __nv_bfloat16 mb = __float2bfloat16(r1);
            float r2 = r1 - __bfloat162float(mb);    // exact
            hv[j] = hb; mv[j] = mb; lv[j] = __float2bfloat16(r2);
        }
        size_t o = i * 4;
        *(__nv_bfloat162*)&hh[o]     = __nv_bfloat162(hv[0], hv[1]);
        *(__nv_bfloat162*)&hh[o + 2] = __nv_bfloat162(hv[2], hv[3]);
        *(__nv_bfloat162*)&mm[o]     = __nv_bfloat162(mv[0], mv[1]);
        *(__nv_bfloat162*)&mm[o + 2] = __nv_bfloat162(mv[2], mv[3]);
        *(__nv_bfloat162*)&ll[o]     = __nv_bfloat162(lv[0], lv[1]);
        *(__nv_bfloat162*)&ll[o + 2] = __nv_bfloat162(lv[2], lv[3]);
    }
}

// ---------------- cp.async helpers ------------------------------------------
__device__ __forceinline__ void cp16(void* sdst, const void* gsrc) {
    uint32_t s = (uint32_t)__cvta_generic_to_shared(sdst);
    asm volatile("cp.async.cg.shared.global [%0], [%1], 16;" :: "r"(s), "l"(gsrc));
}
#define CP_COMMIT() asm volatile("cp.async.commit_group;" ::: "memory")
#define CP_WAIT(n)  asm volatile("cp.async.wait_group %0;" :: "n"(n) : "memory")

// ---------------- bf16 HMMA x6 GEMM: C = A @ B^T (+bias) --------------------
// FROZEN NUMERICS (validated R7/R10/R11/R13/R15): per k16 (ascending), 6
// slice-MMAs in order hh,hm,hl,mh,mm,lh, each issued with C=0, folded into
// fp32 accumulators via packed add.rn.f32x2 (bit-identical per element to
// scalar RN adds). R16 changes ONLY the schedule: K-chunks of 16 with 3-stage
// cp.async and TPAD=24 cut smem to 110.6KB/CTA -> 2 CTAs/SM (4 warps/SMSP)
// while keeping the full 128x128 tile; A-fragments loaded per-pa-group
// (pa0: hh,hm,hl; pa1: mh,mm; pa2: lh), preserving the exact pass order.
#define GT   128
#define KC   16
#define NSTG 3
#define TPAD 24                    // 48B row stride: 16B-aligned, conflict-free
#define TILE_E (128 * TPAD)        // 3072 elems per slice tile
#define BUF_E  (6 * TILE_E)        // 18432 elems (3 A + 3 B slices)
#define SMEM_B (NSTG * BUF_E * 2)  // 110592 bytes

// MMA (C=0) + packed f32x2 RN folds into 64-bit accumulator pairs.
__device__ __forceinline__ void mma_fold(uint64_t& a01, uint64_t& a23,
                                         const uint32_t* a, const uint32_t* b) {
    asm volatile("{\n\t"
        ".reg .f32 t0, t1, t2, t3;\n\t"
        ".reg .b64 p0, p1;\n\t"
        "mma.sync.aligned.m16n8k16.row.col.f32.bf16.bf16.f32 "
        "{t0, t1, t2, t3}, {%2, %3, %4, %5}, {%6, %7}, {%8, %8, %8, %8};\n\t"
        "mov.b64 p0, {t0, t1};\n\t"
        "mov.b64 p1, {t2, t3};\n\t"
        "add.rn.f32x2 %0, %0, p0;\n\t"
        "add.rn.f32x2 %1, %1, p1;\n\t"
        "}"
        : "+l"(a01), "+l"(a23)
        : "r"(a[0]), "r"(a[1]), "r"(a[2]), "r"(a[3]),
          "r"(b[0]), "r"(b[1]), "f"(0.f));
}

__device__ __forceinline__ void preload_chunk(
    __nv_bfloat16* buf, const __nv_bfloat16* const* Ag, const __nv_bfloat16* const* Bg,
    int bm, int bn, int K, int k0, int tid)
{
    const int row = tid >> 1, cu = tid & 1;   // 128 rows x 2 16B-units
#pragma unroll
    for (int s = 0; s < 3; s++) {
        cp16(&buf[s * TILE_E + row * TPAD + cu * 8],
             Ag[s] + (size_t)(bm + row) * K + k0 + cu * 8);
        cp16(&buf[(3 + s) * TILE_E + row * TPAD + cu * 8],
             Bg[s] + (size_t)(bn + row) * K + k0 + cu * 8);
    }
}

__global__ __launch_bounds__(256, 2)
void gemm_mma6(const __nv_bfloat16* __restrict__ A0, const __nv_bfloat16* __restrict__ A1,
               const __nv_bfloat16* __restrict__ A2,
               const __nv_bfloat16* __restrict__ B0, const __nv_bfloat16* __restrict__ B1,
               const __nv_bfloat16* __restrict__ B2,
               const float* __restrict__ bias, float* __restrict__ C,
               int M, int N, int K)
{
    extern __shared__ __nv_bfloat16 sm[];

    const int tid  = threadIdx.x;
    const int wid  = tid >> 5;
    const int lane = tid & 31;
    const int gid  = lane >> 2;          // 0..7
    const int tig  = lane & 3;           // 0..3
    const int bm   = blockIdx.y * GT;
    const int bn   = blockIdx.x * GT;
    const int wm   = (wid >> 2) * 64;    // warp M offset
    const int wn   = (wid & 3) * 32;     // warp N offset

    const __nv_bfloat16* Ag[3] = {A0, A1, A2};
    const __nv_bfloat16* Bg[3] = {B0, B1, B2};

    // accumulators as packed f32x2 pairs: [mf][nf][0]=(c0,c1), [1]=(c2,c3)
    uint64_t acc[4][4][2];
#pragma unroll
    for (int i = 0; i < 4; i++)
#pragma unroll
        for (int j = 0; j < 4; j++) { acc[i][j][0] = 0ull; acc[i][j][1] = 0ull; }

    const int nchunk = K / KC;

    preload_chunk(sm,             Ag, Bg, bm, bn, K, 0,      tid); CP_COMMIT();
    preload_chunk(sm + BUF_E,     Ag, Bg, bm, bn, K, KC,     tid); CP_COMMIT();
    preload_chunk(sm + 2 * BUF_E, Ag, Bg, bm, bn, K, 2 * KC, tid); CP_COMMIT();

    int sbuf = 0;
    for (int c = 0; c < nchunk; c++) {
        CP_WAIT(2);
        __syncthreads();

        __nv_bfloat16* As = sm + sbuf * BUF_E;
        const __nv_bfloat16* Bb0 = As + 3 * TILE_E;

        // B fragments: all 3 slices resident (24 regs)
        uint32_t bfr[3][4][2];
#pragma unroll
        for (int s = 0; s < 3; s++) {
            const __nv_bfloat16* Bb = Bb0 + s * TILE_E;
#pragma unroll
            for (int nf = 0; nf < 4; nf++) {
                int nrow = wn + nf * 8 + gid;
                bfr[s][nf][0] = *(const uint32_t*)&Bb[nrow * TPAD + 2 * tig];
                bfr[s][nf][1] = *(const uint32_t*)&Bb[nrow * TPAD + 2 * tig + 8];
            }
        }
        // pass order per element: hh,hm,hl,mh,mm,lh — grouped by A slice
        const int NPB[3] = {3, 2, 1};
#pragma unroll
        for (int pa = 0; pa < 3; pa++) {
            const __nv_bfloat16* Ab = As + pa * TILE_E;
            uint32_t afr[4][4];
#pragma unroll
            for (int mf = 0; mf < 4; mf++) {
                int r0 = wm + mf * 16 + gid;
                afr[mf][0] = *(const uint32_t*)&Ab[r0 * TPAD + 2 * tig];
                afr[mf][1] = *(const uint32_t*)&Ab[(r0 + 8) * TPAD + 2 * tig];
                afr[mf][2] = *(const uint32_t*)&Ab[r0 * TPAD + 2 * tig + 8];
                afr[mf][3] = *(const uint32_t*)&Ab[(r0 + 8) * TPAD + 2 * tig + 8];
            }
#pragma unroll
            for (int pb = 0; pb < 3; pb++) {
                if (pb < NPB[pa]) {
#pragma unroll
                    for (int mf = 0; mf < 4; mf++)
#pragma unroll
                        for (int nf = 0; nf < 4; nf++)
                            mma_fold(acc[mf][nf][0], acc[mf][nf][1],
                                     afr[mf], bfr[pb][nf]);
                }
            }
        }
        __syncthreads();
        // always commit one group per iteration (empty at tail): CP_WAIT(2)
        // at iter c then always has exactly groups c+1, c+2 newer.
        if (c + 3 < nchunk)
            preload_chunk(sm + sbuf * BUF_E, Ag, Bg, bm, bn, K, (c + 3) * KC, tid);
        CP_COMMIT();
        sbuf = (sbuf == NSTG - 1) ? 0 : sbuf + 1;
    }

    // epilogue: (c0,c1) -> (row, col..col+1), (c2,c3) -> (row+8, ...)
    const bool hb = (bias != nullptr);
#pragma unroll
    for (int mf = 0; mf < 4; mf++) {
#pragma unroll
        for (int nf = 0; nf < 4; nf++) {
            int row = bm + wm + mf * 16 + gid;
            int col = bn + wn + nf * 8 + 2 * tig;
            float v0 = __uint_as_float((uint32_t)(acc[mf][nf][0] & 0xFFFFFFFFull));
            float v1 = __uint_as_float((uint32_t)(acc[mf][nf][0] >> 32));
            float v2 = __uint_as_float((uint32_t)(acc[mf][nf][1] & 0xFFFFFFFFull));
            float v3 = __uint_as_float((uint32_t)(acc[mf][nf][1] >> 32));
            if (hb) {
                float bb0 = bias[col], bb1 = bias[col + 1];
                v0 = __fadd_rn(v0, bb0); v1 = __fadd_rn(v1, bb1);
                v2 = __fadd_rn(v2, bb0); v3 = __fadd_rn(v3, bb1);
            }
            *(float2*)&C[(size_t)row * N + col]       = make_float2(v0, v1);
            *(float2*)&C[(size_t)(row + 8) * N + col] = make_float2(v2, v3);
        }
    }
}

// ---------------- gating + exact k-winners (+ fused h split) ----------------
__global__ __launch_bounds__(256)
void gate_topk(const float* __restrict__ y, const float* __restrict__ dend,
               __nv_bfloat16* __restrict__ hh, __nv_bfloat16* __restrict__ hm,
               __nv_bfloat16* __restrict__ hl)
{
    __shared__ float     vals[HID];
    __shared__ unsigned  keys[HID];
    __shared__ int       hist[256];
    __shared__ unsigned  s_prefix;
    __shared__ int       s_remaining;

    const int b   = blockIdx.x;
    const int tid = threadIdx.x;
    const float* drow = dend + (size_t)b * HID * NSEG;
    const float* yrow = y    + (size_t)b * HID;

    for (int h = tid; h < HID; h += 256) {
        const float2* d2 = (const float2*)(drow + (size_t)h * NSEG);
        float sv[NSEG];
#pragma unroll
        for (int q = 0; q < 5; q++) {
            float2 vv = d2[q];
            sv[2 * q] = vv.x; sv[2 * q + 1] = vv.y;
        }
        float best = 0.f, bestabs = -1.f;
#pragma unroll
        for (int s = 0; s < NSEG; s++) {
            float a = fabsf(sv[s]);
            if (a > bestabs) { bestabs = a; best = sv[s]; }  // first-occurrence argmax
        }
        float g = yrow[h] * (1.f / (1.f + expf(-best)));
        vals[h] = g;
        unsigned u = __float_as_uint(g);
        keys[h] = (u & 0x80000000u) ? ~u : (u | 0x80000000u);
    }
    if (tid == 0) { s_prefix = 0u; s_remaining = KWIN; }
    __syncthreads();

    for (int d = 3; d >= 0; d--) {
        hist[tid] = 0;
        __syncthreads();
        const unsigned pmask = (d == 3) ? 0u : (0xFFFFFFFFu << ((d + 1) * 8));
        const unsigned pref  = s_prefix;
        const int shift = d * 8;
        for (int h = tid; h < HID; h += 256) {
            unsigned kk = keys[h];
            if ((kk & pmask) == pref)
                atomicAdd(&hist[(kk >> shift) & 0xFF], 1);
        }
        __syncthreads();
        if (tid == 0) {
            int rem = s_remaining, cum = 0, bkt = 255;
            for (; bkt > 0; bkt--) {
                int c = hist[bkt];
                if (cum + c >= rem) break;
                cum += c;
            }
            s_remaining = rem - cum;
            s_prefix    = pref | ((unsigned)bkt << shift);
        }
        __syncthreads();
    }

    const unsigned kth = s_prefix;
    for (int h = tid; h < HID; h += 256) {
        float v = (keys[h] >= kth) ? vals[h] : 0.f;
        size_t o = (size_t)b * HID + h;
        __nv_bfloat16 hb = __float2bfloat16(v);
        float hf = __bfloat162float(hb);
        float r1 = v - hf;
        __nv_bfloat16 mb = __float2bfloat16(r1);
        float r2 = r1 - __bfloat162float(mb);
        hh[o] = hb; hm[o] = mb; hl[o] = __float2bfloat16(r2);
    }
}

// ---------------- launch -----------------------------------------------------
extern "C" void kernel_launch(void* const* d_in, const int* in_sizes, int n_in,
                              void* d_out, int out_size)
{
    (void)in_sizes; (void)n_in; (void)out_size;
    const float* x     = (const float*)d_in[0];
    const float* ctx   = (const float*)d_in[1];
    const float* w1    = (const float*)d_in[2];
    const float* b1    = (const float*)d_in[3];
    const float* seg1  = (const float*)d_in[4];
    const float* w2    = (const float*)d_in[5];
    const float* b2    = (const float*)d_in[6];
    const float* seg2  = (const float*)d_in[7];
    const float* w_out = (const float*)d_in[8];
    const float* b_out = (const float*)d_in[9];
    float* out = (float*)d_out;

    float *dendp, *yp;
    cudaGetSymbolAddress((void**)&dendp, g_dend);
    cudaGetSymbolAddress((void**)&yp,    g_y);
    __nv_bfloat16 *xs, *cs, *w1s, *s1s, *w2s, *s2s, *wos, *hs;
    cudaGetSymbolAddress((void**)&xs,  g_xs);
    cudaGetSymbolAddress((void**)&cs,  g_cs);
    cudaGetSymbolAddress((void**)&w1s, g_w1s);
    cudaGetSymbolAddress((void**)&s1s, g_s1s);
    cudaGetSymbolAddress((void**)&w2s, g_w2s);
    cudaGetSymbolAddress((void**)&s2s, g_s2s);
    cudaGetSymbolAddress((void**)&wos, g_wos);
    cudaGetSymbolAddress((void**)&hs,  g_hs);

    const size_t nx = (size_t)B_SZ * D_IN,  nc = (size_t)B_SZ * D_CTX;
    const size_t n1 = (size_t)HID * D_IN,   ns = (size_t)HID * NSEG * D_CTX;
    const size_t n2 = (size_t)HID * HID,    no = (size_t)D_OUT * HID;
    const size_t nh = (size_t)B_SZ * HID;

    cudaFuncSetAttribute(gemm_mma6, cudaFuncAttributeMaxDynamicSharedMemorySize, SMEM_B);

    split_kernel<<<1024, 256>>>(x,     xs,  xs + nx,  xs + 2*nx,  nx);
    split_kernel<<<1024, 256>>>(ctx,   cs,  cs + nc,  cs + 2*nc,  nc);
    split_kernel<<<1024, 256>>>(w1,    w1s, w1s + n1, w1s + 2*n1, n1);
    split_kernel<<<2048, 256>>>(seg1,  s1s, s1s + ns, s1s + 2*ns, ns);
    split_kernel<<<1024, 256>>>(w2,    w2s, w2s + n2, w2s + 2*n2, n2);
    split_kernel<<<2048, 256>>>(seg2,  s2s, s2s + ns, s2s + 2*ns, ns);
    split_kernel<<<1024, 256>>>(w_out, wos, wos + no, wos + 2*no, no);

    // layer 1
    gemm_mma6<<<dim3(HID / GT, B_SZ / GT), 256, SMEM_B>>>(
        xs, xs + nx, xs + 2*nx, w1s, w1s + n1, w1s + 2*n1, b1, yp, B_SZ, HID, D_IN);
    gemm_mma6<<<dim3(HID * NSEG / GT, B_SZ / GT), 256, SMEM_B>>>(
        cs, cs + nc, cs + 2*nc, s1s, s1s + ns, s1s + 2*ns, nullptr, dendp, B_SZ, HID * NSEG, D_CTX);
    gate_topk<<<B_SZ, 256>>>(yp, dendp, hs, hs + nh, hs + 2*nh);

    // layer 2
    gemm_mma6<<<dim3(HID / GT, B_SZ / GT), 256, SMEM_B>>>(
        hs, hs + nh, hs + 2*nh, w2s, w2s + n2, w2s + 2*n2, b2, yp, B_SZ, HID, HID);
    gemm_mma6<<<dim3(HID * NSEG / GT, B_SZ / GT), 256, SMEM_B>>>(
        cs, cs + nc, cs + 2*nc, s2s, s2s + ns, s2s + 2*ns, nullptr, dendp, B_SZ, HID * NSEG, D_CTX);
    gate_topk<<<B_SZ, 256>>>(yp, dendp, hs, hs + nh, hs + 2*nh);

    // output projection
    gemm_mma6<<<dim3(D_OUT / GT, B_SZ / GT), 256, SMEM_B>>>(
        hs, hs + nh, hs + 2*nh, wos, wos + no, wos + 2*no, b_out, out, B_SZ, D_OUT, HID);
}

// round 17
// speedup vs baseline: 1.1144x; 1.1144x over previous
#include <cuda_runtime.h>
#include <cuda_bf16.h>
#include <math.h>
#include <stdint.h>

#define B_SZ  4096
#define D_IN  1024
#define HID   2048
#define NSEG  10
#define D_CTX 1024
#define D_OUT 1024
#define KWIN  102

// ---------------- scratch (device globals, allocation-free) ----------------
__device__ float g_dend[(size_t)B_SZ * HID * NSEG]; // 4096 x 20480  (~335 MB)
__device__ float g_y[(size_t)B_SZ * HID];           // pre-gate linear output

// bf16 hi/mid/lo splits of every GEMM operand (exact 3-way decomposition)
__device__ __nv_bfloat16 g_xs [3][(size_t)B_SZ * D_IN];
__device__ __nv_bfloat16 g_cs [3][(size_t)B_SZ * D_CTX];
__device__ __nv_bfloat16 g_w1s[3][(size_t)HID * D_IN];
__device__ __nv_bfloat16 g_s1s[3][(size_t)HID * NSEG * D_CTX];
__device__ __nv_bfloat16 g_w2s[3][(size_t)HID * HID];
__device__ __nv_bfloat16 g_s2s[3][(size_t)HID * NSEG * D_CTX];
__device__ __nv_bfloat16 g_wos[3][(size_t)D_OUT * HID];
__device__ __nv_bfloat16 g_hs [3][(size_t)B_SZ * HID];

// ---------------- bf16 3-way split (float4-vectorized) ----------------------
__global__ void split_kernel(const float* __restrict__ src,
                             __nv_bfloat16* __restrict__ hh,
                             __nv_bfloat16* __restrict__ mm,
                             __nv_bfloat16* __restrict__ ll, size_t n)
{
    const size_t n4 = n >> 2;
    for (size_t i = (size_t)blockIdx.x * blockDim.x + threadIdx.x; i < n4;
         i += (size_t)gridDim.x * blockDim.x) {
        float4 a = ((const float4*)src)[i];
        float av[4] = {a.x, a.y, a.z, a.w};
        __nv_bfloat16 hv[4], mv[4], lv[4];
#pragma unroll
        for (int j = 0; j < 4; j++) {
            float v = av[j];
            __nv_bfloat16 hb = __float2bfloat16(v);
            float hf = __bfloat162float(hb);
            float r1 = v - hf;                       // exact
            __nv_bfloat16 mb = __float2bfloat16(r1);
            float r2 = r1 - __bfloat162float(mb);    // exact
            hv[j] = hb; mv[j] = mb; lv[j] = __float2bfloat16(r2);
        }
        size_t o = i * 4;
        *(__nv_bfloat162*)&hh[o]     = __nv_bfloat162(hv[0], hv[1]);
        *(__nv_bfloat162*)&hh[o + 2] = __nv_bfloat162(hv[2], hv[3]);
        *(__nv_bfloat162*)&mm[o]     = __nv_bfloat162(mv[0], mv[1]);
        *(__nv_bfloat162*)&mm[o + 2] = __nv_bfloat162(mv[2], mv[3]);
        *(__nv_bfloat162*)&ll[o]     = __nv_bfloat162(lv[0], lv[1]);
        *(__nv_bfloat162*)&ll[o + 2] = __nv_bfloat162(lv[2], lv[3]);
    }
}

// ---------------- cp.async helpers ------------------------------------------
__device__ __forceinline__ void cp16(void* sdst, const void* gsrc) {
    uint32_t s = (uint32_t)__cvta_generic_to_shared(sdst);
    asm volatile("cp.async.cg.shared.global [%0], [%1], 16;" :: "r"(s), "l"(gsrc));
}
#define CP_COMMIT() asm volatile("cp.async.commit_group;" ::: "memory")
#define CP_WAIT(n)  asm volatile("cp.async.wait_group %0;" :: "n"(n) : "memory")

#define LDSM_X4(r0, r1, r2, r3, addr) \
    asm volatile("ldmatrix.sync.aligned.m8n8.x4.shared.b16 {%0,%1,%2,%3}, [%4];" \
                 : "=r"(r0), "=r"(r1), "=r"(r2), "=r"(r3) : "r"(addr))

// ---------------- bf16 HMMA x6 GEMM: C = A @ B^T (+bias) --------------------
// FROZEN NUMERICS (validated R7/R10/R11/R13/R15): per k16 (ascending), 6
// slice-MMAs in order hh,hm,hl,mh,mm,lh, each issued with C=0, folded into
// fp32 accumulators via packed add.rn.f32x2 (bit-identical per element to
// scalar RN adds). R17 changes ONLY the load path and barrier schedule:
// ldmatrix.x4 fragment loads (36 LDSM vs 144 LDS per warp/chunk, identical
// values/registers) and a single-__syncthreads pipeline (preload issued after
// the barrier into the buffer freed last iteration; CP_WAIT(1) + always-commit
// keeps cp.async group accounting exact).
#define GT   128
#define KC   32
#define NSTG 3
#define TPAD 40                    // smem row stride in bf16 (conflict-free)
#define TILE_E (128 * TPAD)        // elements per slice tile
#define BUF_E  (6 * TILE_E)        // 3 A slices + 3 B slices
#define SMEM_B (NSTG * BUF_E * 2)  // bytes (184320)

// MMA (C=0) + packed f32x2 RN folds into 64-bit accumulator pairs.
__device__ __forceinline__ void mma_fold(uint64_t& a01, uint64_t& a23,
                                         const uint32_t* a, const uint32_t* b) {
    asm volatile("{\n\t"
        ".reg .f32 t0, t1, t2, t3;\n\t"
        ".reg .b64 p0, p1;\n\t"
        "mma.sync.aligned.m16n8k16.row.col.f32.bf16.bf16.f32 "
        "{t0, t1, t2, t3}, {%2, %3, %4, %5}, {%6, %7}, {%8, %8, %8, %8};\n\t"
        "mov.b64 p0, {t0, t1};\n\t"
        "mov.b64 p1, {t2, t3};\n\t"
        "add.rn.f32x2 %0, %0, p0;\n\t"
        "add.rn.f32x2 %1, %1, p1;\n\t"
        "}"
        : "+l"(a01), "+l"(a23)
        : "r"(a[0]), "r"(a[1]), "r"(a[2]), "r"(a[3]),
          "r"(b[0]), "r"(b[1]), "f"(0.f));
}

__device__ __forceinline__ void preload_chunk(
    __nv_bfloat16* buf, const __nv_bfloat16* const* Ag, const __nv_bfloat16* const* Bg,
    int bm, int bn, int K, int k0, int tid)
{
#pragma unroll
    for (int s = 0; s < 3; s++) {
#pragma unroll
        for (int q = 0; q < 2; q++) {
            int u   = tid + 256 * q;       // 512 16B units per tile
            int row = u >> 2;
            int cu  = u & 3;
            cp16(&buf[s * TILE_E + row * TPAD + cu * 8],
                 Ag[s] + (size_t)(bm + row) * K + k0 + cu * 8);
            cp16(&buf[(3 + s) * TILE_E + row * TPAD + cu * 8],
                 Bg[s] + (size_t)(bn + row) * K + k0 + cu * 8);
        }
    }
}

__global__ __launch_bounds__(256, 1)
void gemm_mma6(const __nv_bfloat16* __restrict__ A0, const __nv_bfloat16* __restrict__ A1,
               const __nv_bfloat16* __restrict__ A2,
               const __nv_bfloat16* __restrict__ B0, const __nv_bfloat16* __restrict__ B1,
               const __nv_bfloat16* __restrict__ B2,
               const float* __restrict__ bias, float* __restrict__ C,
               int M, int N, int K)
{
    extern __shared__ __nv_bfloat16 sm[];

    const int tid  = threadIdx.x;
    const int wid  = tid >> 5;
    const int lane = tid & 31;
    const int gid  = lane >> 2;          // 0..7
    const int tig  = lane & 3;           // 0..3
    const int bm   = blockIdx.y * GT;
    const int bn   = blockIdx.x * GT;
    const int wm   = (wid >> 2) * 64;    // warp M offset
    const int wn   = (wid & 3) * 32;     // warp N offset

    const __nv_bfloat16* Ag[3] = {A0, A1, A2};
    const __nv_bfloat16* Bg[3] = {B0, B1, B2};

    // ldmatrix lane addressing (byte offsets within a stage buffer)
    const int grp  = lane >> 3;          // 0..3
    const int lrow = lane & 7;           // 0..7
    // A x4 tile order: (m0-7,k0-7),(m8-15,k0-7),(m0-7,k8-15),(m8-15,k8-15)
    uint32_t aoff[3][4];
#pragma unroll
    for (int s = 0; s < 3; s++)
#pragma unroll
        for (int mf = 0; mf < 4; mf++) {
            int row = wm + mf * 16 + (grp & 1) * 8 + lrow;
            int ko  = (grp >> 1) * 8;
            aoff[s][mf] = (uint32_t)((s * TILE_E + row * TPAD + ko) * 2);
        }
    // B x4 tile order: (n(2p),k0-7),(n(2p),k8-15),(n(2p+1),k0-7),(n(2p+1),k8-15)
    uint32_t boff[3][2];
#pragma unroll
    for (int s = 0; s < 3; s++)
#pragma unroll
        for (int p = 0; p < 2; p++) {
            int row = wn + (2 * p + (grp >> 1)) * 8 + lrow;
            int ko  = (grp & 1) * 8;
            boff[s][p] = (uint32_t)(((3 + s) * TILE_E + row * TPAD + ko) * 2);
        }

    const uint32_t smem_base = (uint32_t)__cvta_generic_to_shared(sm);

    // accumulators as packed f32x2 pairs: [mf][nf][0]=(c0,c1), [1]=(c2,c3)
    uint64_t acc[4][4][2];
#pragma unroll
    for (int i = 0; i < 4; i++)
#pragma unroll
        for (int j = 0; j < 4; j++) { acc[i][j][0] = 0ull; acc[i][j][1] = 0ull; }

    const int nchunk = K / KC;

    preload_chunk(sm,         Ag, Bg, bm, bn, K, 0,  tid); CP_COMMIT();
    preload_chunk(sm + BUF_E, Ag, Bg, bm, bn, K, KC, tid); CP_COMMIT();

    int sbuf = 0;
    for (int c = 0; c < nchunk; c++) {
        CP_WAIT(1);              // chunk c landed (group c+1 may be in flight)
        __syncthreads();
        // preload chunk c+2 into the buffer freed at iteration c-1
        if (c + 2 < nchunk)
            preload_chunk(sm + ((sbuf + 2) % NSTG) * BUF_E,
                          Ag, Bg, bm, bn, K, (c + 2) * KC, tid);
        CP_COMMIT();             // always commit (empty at tail) for accounting

        const uint32_t stage = smem_base + (uint32_t)(sbuf * BUF_E * 2);

#pragma unroll
        for (int ks = 0; ks < 2; ks++) {
            const uint32_t kbb = ks * 32;       // 16 bf16 = 32 bytes
            uint32_t afr[3][4][4], bfr[3][4][2];
#pragma unroll
            for (int s = 0; s < 3; s++) {
#pragma unroll
                for (int mf = 0; mf < 4; mf++)
                    LDSM_X4(afr[s][mf][0], afr[s][mf][1], afr[s][mf][2], afr[s][mf][3],
                            stage + aoff[s][mf] + kbb);
#pragma unroll
                for (int p = 0; p < 2; p++)
                    LDSM_X4(bfr[s][2 * p][0], bfr[s][2 * p][1],
                            bfr[s][2 * p + 1][0], bfr[s][2 * p + 1][1],
                            stage + boff[s][p] + kbb);
            }
            // 6 slice-MMAs per k16: hh,hm,hl,mh,mm,lh — C=0 + packed RN folds
            const int PA[6] = {0, 0, 0, 1, 1, 2};
            const int PB[6] = {0, 1, 2, 0, 1, 0};
#pragma unroll
            for (int p = 0; p < 6; p++) {
                const int pa = PA[p], pb = PB[p];
#pragma unroll
                for (int mf = 0; mf < 4; mf++)
#pragma unroll
                    for (int nf = 0; nf < 4; nf++)
                        mma_fold(acc[mf][nf][0], acc[mf][nf][1],
                                 afr[pa][mf], bfr[pb][nf]);
            }
        }
        sbuf = (sbuf == NSTG - 1) ? 0 : sbuf + 1;
    }

    // epilogue: (c0,c1) -> (row, col..col+1), (c2,c3) -> (row+8, ...)
    const bool hb = (bias != nullptr);
#pragma unroll
    for (int mf = 0; mf < 4; mf++) {
#pragma unroll
        for (int nf = 0; nf < 4; nf++) {
            int row = bm + wm + mf * 16 + gid;
            int col = bn + wn + nf * 8 + 2 * tig;
            float v0 = __uint_as_float((uint32_t)(acc[mf][nf][0] & 0xFFFFFFFFull));
            float v1 = __uint_as_float((uint32_t)(acc[mf][nf][0] >> 32));
            float v2 = __uint_as_float((uint32_t)(acc[mf][nf][1] & 0xFFFFFFFFull));
            float v3 = __uint_as_float((uint32_t)(acc[mf][nf][1] >> 32));
            if (hb) {
                float bb0 = bias[col], bb1 = bias[col + 1];
                v0 = __fadd_rn(v0, bb0); v1 = __fadd_rn(v1, bb1);
                v2 = __fadd_rn(v2, bb0); v3 = __fadd_rn(v3, bb1);
            }
            *(float2*)&C[(size_t)row * N + col]       = make_float2(v0, v1);
            *(float2*)&C[(size_t)(row + 8) * N + col] = make_float2(v2, v3);
        }
    }
}

// ---------------- gating + exact k-winners (+ fused h split) ----------------
__global__ __launch_bounds__(256)
void gate_topk(const float* __restrict__ y, const float* __restrict__ dend,
               __nv_bfloat16* __restrict__ hh, __nv_bfloat16* __restrict__ hm,
               __nv_bfloat16* __restrict__ hl)
{
    __shared__ float     vals[HID];
    __shared__ unsigned  keys[HID];
    __shared__ int       hist[256];
    __shared__ unsigned  s_prefix;
    __shared__ int       s_remaining;

    const int b   = blockIdx.x;
    const int tid = threadIdx.x;
    const float* drow = dend + (size_t)b * HID * NSEG;
    const float* yrow = y    + (size_t)b * HID;

    for (int h = tid; h < HID; h += 256) {
        const float2* d2 = (const float2*)(drow + (size_t)h * NSEG);
        float sv[NSEG];
#pragma unroll
        for (int q = 0; q < 5; q++) {
            float2 vv = d2[q];
            sv[2 * q] = vv.x; sv[2 * q + 1] = vv.y;
        }
        float best = 0.f, bestabs = -1.f;
#pragma unroll
        for (int s = 0; s < NSEG; s++) {
            float a = fabsf(sv[s]);
            if (a > bestabs) { bestabs = a; best = sv[s]; }  // first-occurrence argmax
        }
        float g = yrow[h] * (1.f / (1.f + expf(-best)));
        vals[h] = g;
        unsigned u = __float_as_uint(g);
        keys[h] = (u & 0x80000000u) ? ~u : (u | 0x80000000u);
    }
    if (tid == 0) { s_prefix = 0u; s_remaining = KWIN; }
    __syncthreads();

    for (int d = 3; d >= 0; d--) {
        hist[tid] = 0;
        __syncthreads();
        const unsigned pmask = (d == 3) ? 0u : (0xFFFFFFFFu << ((d + 1) * 8));
        const unsigned pref  = s_prefix;
        const int shift = d * 8;
        for (int h = tid; h < HID; h += 256) {
            unsigned kk = keys[h];
            if ((kk & pmask) == pref)
                atomicAdd(&hist[(kk >> shift) & 0xFF], 1);
        }
        __syncthreads();
        if (tid == 0) {
            int rem = s_remaining, cum = 0, bkt = 255;
            for (; bkt > 0; bkt--) {
                int c = hist[bkt];
                if (cum + c >= rem) break;
                cum += c;
            }
            s_remaining = rem - cum;
            s_prefix    = pref | ((unsigned)bkt << shift);
        }
        __syncthreads();
    }

    const unsigned kth = s_prefix;
    for (int h = tid; h < HID; h += 256) {
        float v = (keys[h] >= kth) ? vals[h] : 0.f;
        size_t o = (size_t)b * HID + h;
        __nv_bfloat16 hb = __float2bfloat16(v);
        float hf = __bfloat162float(hb);
        float r1 = v - hf;
        __nv_bfloat16 mb = __float2bfloat16(r1);
        float r2 = r1 - __bfloat162float(mb);
        hh[o] = hb; hm[o] = mb; hl[o] = __float2bfloat16(r2);
    }
}

// ---------------- launch -----------------------------------------------------
extern "C" void kernel_launch(void* const* d_in, const int* in_sizes, int n_in,
                              void* d_out, int out_size)
{
    (void)in_sizes; (void)n_in; (void)out_size;
    const float* x     = (const float*)d_in[0];
    const float* ctx   = (const float*)d_in[1];
    const float* w1    = (const float*)d_in[2];
    const float* b1    = (const float*)d_in[3];
    const float* seg1  = (const float*)d_in[4];
    const float* w2    = (const float*)d_in[5];
    const float* b2    = (const float*)d_in[6];
    const float* seg2  = (const float*)d_in[7];
    const float* w_out = (const float*)d_in[8];
    const float* b_out = (const float*)d_in[9];
    float* out = (float*)d_out;

    float *dendp, *yp;
    cudaGetSymbolAddress((void**)&dendp, g_dend);
    cudaGetSymbolAddress((void**)&yp,    g_y);
    __nv_bfloat16 *xs, *cs, *w1s, *s1s, *w2s, *s2s, *wos, *hs;
    cudaGetSymbolAddress((void**)&xs,  g_xs);
    cudaGetSymbolAddress((void**)&cs,  g_cs);
    cudaGetSymbolAddress((void**)&w1s, g_w1s);
    cudaGetSymbolAddress((void**)&s1s, g_s1s);
    cudaGetSymbolAddress((void**)&w2s, g_w2s);
    cudaGetSymbolAddress((void**)&s2s, g_s2s);
    cudaGetSymbolAddress((void**)&wos, g_wos);
    cudaGetSymbolAddress((void**)&hs,  g_hs);

    const size_t nx = (size_t)B_SZ * D_IN,  nc = (size_t)B_SZ * D_CTX;
    const size_t n1 = (size_t)HID * D_IN,   ns = (size_t)HID * NSEG * D_CTX;
    const size_t n2 = (size_t)HID * HID,    no = (size_t)D_OUT * HID;
    const size_t nh = (size_t)B_SZ * HID;

    cudaFuncSetAttribute(gemm_mma6, cudaFuncAttributeMaxDynamicSharedMemorySize, SMEM_B);

    split_kernel<<<1024, 256>>>(x,     xs,  xs + nx,  xs + 2*nx,  nx);
    split_kernel<<<1024, 256>>>(ctx,   cs,  cs + nc,  cs + 2*nc,  nc);
    split_kernel<<<1024, 256>>>(w1,    w1s, w1s + n1, w1s + 2*n1, n1);
    split_kernel<<<2048, 256>>>(seg1,  s1s, s1s + ns, s1s + 2*ns, ns);
    split_kernel<<<1024, 256>>>(w2,    w2s, w2s + n2, w2s + 2*n2, n2);
    split_kernel<<<2048, 256>>>(seg2,  s2s, s2s + ns, s2s + 2*ns, ns);
    split_kernel<<<1024, 256>>>(w_out, wos, wos + no, wos + 2*no, no);

    // layer 1
    gemm_mma6<<<dim3(HID / GT, B_SZ / GT), 256, SMEM_B>>>(
        xs, xs + nx, xs + 2*nx, w1s, w1s + n1, w1s + 2*n1, b1, yp, B_SZ, HID, D_IN);
    gemm_mma6<<<dim3(HID * NSEG / GT, B_SZ / GT), 256, SMEM_B>>>(
        cs, cs + nc, cs + 2*nc, s1s, s1s + ns, s1s + 2*ns, nullptr, dendp, B_SZ, HID * NSEG, D_CTX);
    gate_topk<<<B_SZ, 256>>>(yp, dendp, hs, hs + nh, hs + 2*nh);

    // layer 2
    gemm_mma6<<<dim3(HID / GT, B_SZ / GT), 256, SMEM_B>>>(
        hs, hs + nh, hs + 2*nh, w2s, w2s + n2, w2s + 2*n2, b2, yp, B_SZ, HID, HID);
    gemm_mma6<<<dim3(HID * NSEG / GT, B_SZ / GT), 256, SMEM_B>>>(
        cs, cs + nc, cs + 2*nc, s2s, s2s + ns, s2s + 2*ns, nullptr, dendp, B_SZ, HID * NSEG, D_CTX);
    gate_topk<<<B_SZ, 256>>>(yp, dendp, hs, hs + nh, hs + 2*nh);

    // output projection
    gemm_mma6<<<dim3(D_OUT / GT, B_SZ / GT), 256, SMEM_B>>>(
        hs, hs + nh, hs + 2*nh, wos, wos + no, wos + 2*no, b_out, out, B_SZ, D_OUT, HID);
}